// round 8
// baseline (speedup 1.0000x reference)
#include <cuda_runtime.h>
#include <cstdint>
#include <float.h>

#define N_NODES 100000
#define N_EDGES 2000000
#define HID 32
#define NCLS 40
#define NODE_BLOCKS 3125   // 100000 / 32 nodes per block (8 warps x 4 nodes)

typedef unsigned long long ull;

// ---------------- scratch (static device memory; no allocation) ----------------
__device__ float g_h1 [N_NODES * HID];
__device__ float g_m1 [N_NODES * HID];
__device__ float g_agg1[N_NODES * HID];
__device__ float g_h2 [N_NODES * NCLS];
__device__ float g_m2 [N_NODES * NCLS];
__device__ float g_agg2[N_NODES * NCLS];

// packed duplicated weights (w,w) as f32x2
__device__ __align__(16) ull g_wp1pk[32 * 32];    // [k][c]
__device__ __align__(16) ull g_wm1pk[32 * 32];
__device__ __align__(16) ull g_wi1pk[32 * 96];    // [k][r] transposed
__device__ __align__(16) ull g_wh1pk[32 * 96];
__device__ __align__(16) ull g_wp2pk[32 * 40];    // [k][c]
__device__ __align__(16) ull g_wm2pk[40 * 40];
__device__ __align__(16) ull g_wi2pk[40 * 120];   // [k][r] transposed
__device__ __align__(16) ull g_wh2pk[40 * 120];

__device__ __forceinline__ ull pack2(float a, float b) {
    ull r; asm("mov.b64 %0, {%1, %2};" : "=l"(r) : "f"(a), "f"(b)); return r;
}
__device__ __forceinline__ void unpack2(ull v, float& a, float& b) {
    asm("mov.b64 {%0, %1}, %2;" : "=f"(a), "=f"(b) : "l"(v));
}
__device__ __forceinline__ void fma2(ull& d, ull a, ull b) {
    asm("fma.rn.f32x2 %0, %1, %2, %0;" : "+l"(d) : "l"(a), "l"(b));
}
__device__ __forceinline__ void red_add_v4(float* addr, float4 v) {
    asm volatile("red.global.add.v4.f32 [%0], {%1,%2,%3,%4};"
                 :: "l"(addr), "f"(v.x), "f"(v.y), "f"(v.z), "f"(v.w)
                 : "memory");
}

// ---------------- K0: prepack duplicated weights ----------------
__global__ void k_prepack(const float* __restrict__ W1p, const float* __restrict__ W1m,
                          const float* __restrict__ wih1, const float* __restrict__ whh1,
                          const float* __restrict__ W2p, const float* __restrict__ W2m,
                          const float* __restrict__ wih2, const float* __restrict__ whh2) {
    int t = blockIdx.x * blockDim.x + threadIdx.x;
    int stride = gridDim.x * blockDim.x;
    for (int i = t; i < 1024; i += stride) {       // proj1 weights [k][c] row-major already
        g_wp1pk[i] = pack2(W1p[i], W1p[i]);
        g_wm1pk[i] = pack2(W1m[i], W1m[i]);
    }
    for (int i = t; i < 96 * 32; i += stride) {    // gru1: src [r][k] -> dst [k][r]
        int r = i >> 5, k = i & 31;
        g_wi1pk[k * 96 + r] = pack2(wih1[i], wih1[i]);
        g_wh1pk[k * 96 + r] = pack2(whh1[i], whh1[i]);
    }
    for (int i = t; i < 32 * 40; i += stride)      // proj2 [k][c]
        g_wp2pk[i] = pack2(W2p[i], W2p[i]);
    for (int i = t; i < 40 * 40; i += stride)      // msg2 [k][c]
        g_wm2pk[i] = pack2(W2m[i], W2m[i]);
    for (int i = t; i < 120 * 40; i += stride) {   // gru2: src [r][k] -> dst [k][r]
        int r = i / 40, k = i % 40;
        g_wi2pk[k * 120 + r] = pack2(wih2[i], wih2[i]);
        g_wh2pk[k * 120 + r] = pack2(whh2[i], whh2[i]);
    }
}

// ---------------- K1: proj1 (f32x2, 4 nodes/warp) ----------------
__global__ void __launch_bounds__(256) k_proj1(const float* __restrict__ x) {
    __shared__ ull sWp[1024];
    __shared__ ull sWm[1024];
    __shared__ ull sStg[8 * 64];    // per warp: in01[32], in23[32]
    int t = threadIdx.x;
    {   // copy packed weights (16B vectors)
        const ulonglong2* a = (const ulonglong2*)g_wp1pk;
        const ulonglong2* b = (const ulonglong2*)g_wm1pk;
        ulonglong2* sa = (ulonglong2*)sWp;
        ulonglong2* sb = (ulonglong2*)sWm;
        for (int i = t; i < 512; i += 256) { sa[i] = a[i]; sb[i] = b[i]; }
    }
    __syncthreads();

    int lane = t & 31;
    int warp = t >> 5;
    int n0 = blockIdx.x * 32 + warp * 4;
    ull* my = &sStg[warp * 64];
    float* myf = (float*)my;

    // stage x packed: my[k] = (x[n0][k], x[n1][k]); my[32+k] = (x[n2][k], x[n3][k])
#pragma unroll
    for (int i = 0; i < 4; i++) {
        float v = x[(n0 + i) * 32 + lane];
        myf[(((i >> 1) * 32) + lane) * 2 + (i & 1)] = v;
    }
    __syncwarp();

    ull h01 = 0, h23 = 0;
#pragma unroll 8
    for (int k = 0; k < 32; k++) {
        ull i01 = my[k], i23 = my[32 + k];
        ull w = sWp[k * 32 + lane];
        fma2(h01, i01, w);
        fma2(h23, i23, w);
    }
    // stage h packed (reuse regions)
    __syncwarp();
    my[lane] = h01;
    my[32 + lane] = h23;
    __syncwarp();

    ull m01 = 0, m23 = 0;
#pragma unroll 8
    for (int k = 0; k < 32; k++) {
        ull i01 = my[k], i23 = my[32 + k];
        ull w = sWm[k * 32 + lane];
        fma2(m01, i01, w);
        fma2(m23, i23, w);
    }

    float h0, h1, h2, h3, m0, m1, m2, m3;
    unpack2(h01, h0, h1); unpack2(h23, h2, h3);
    unpack2(m01, m0, m1); unpack2(m23, m2, m3);
    float hs[4] = {h0, h1, h2, h3};
    float ms[4] = {m0, m1, m2, m3};
#pragma unroll
    for (int i = 0; i < 4; i++) {
        int idx = (n0 + i) * 32 + lane;
        g_h1[idx] = hs[i];
        g_m1[idx] = ms[i];
        g_agg1[idx] = 0.f;
    }
}

// ---------------- K2: edge scatter layer 1 (2 edges/thread, red.v4) ----------------
__global__ void k_edge1(const int* __restrict__ ei,
                        const float* __restrict__ ew) {
    int tid = blockIdx.x * 256 + threadIdx.x;   // 8M threads exactly
    int e = tid >> 3;
    int q = tid & 7;
    int e2 = e + N_EDGES / 2;
    int s0 = ei[e],  d0 = ei[N_EDGES + e];  float w0 = ew[e];
    int s1 = ei[e2], d1 = ei[N_EDGES + e2]; float w1 = ew[e2];
    float4 a = *(const float4*)&g_m1[s0 * 32 + q * 4];
    float4 b = *(const float4*)&g_m1[s1 * 32 + q * 4];
    a.x *= w0; a.y *= w0; a.z *= w0; a.w *= w0;
    b.x *= w1; b.y *= w1; b.z *= w1; b.w *= w1;
    red_add_v4(&g_agg1[d0 * 32 + q * 4], a);
    red_add_v4(&g_agg1[d1 * 32 + q * 4], b);
}

// ------- K3: GRU1 + ReLU + proj2 + msg2 fused (f32x2, 4 nodes/warp) --------
__global__ void __launch_bounds__(256) k_gru1_proj2(
                             const float* __restrict__ bih,
                             const float* __restrict__ bhh) {
    extern __shared__ ull dyn1[];
    ull* wi2 = dyn1;                 // 32*96
    ull* wh2 = wi2 + 32 * 96;        // 32*96
    ull* wp2 = wh2 + 32 * 96;        // 32*40
    ull* wm2 = wp2 + 32 * 40;        // 40*40
    ull* stg = wm2 + 40 * 40;        // 8*128

    int t = threadIdx.x;
    {   // copy packed weights: 3072+3072+1280+1600 = 9024 ull = 4512 ull2
        const ulonglong2* a = (const ulonglong2*)g_wi1pk;
        const ulonglong2* b = (const ulonglong2*)g_wh1pk;
        const ulonglong2* c = (const ulonglong2*)g_wp2pk;
        const ulonglong2* d = (const ulonglong2*)g_wm2pk;
        ulonglong2* sa = (ulonglong2*)wi2;
        ulonglong2* sb = (ulonglong2*)wh2;
        ulonglong2* sc = (ulonglong2*)wp2;
        ulonglong2* sd = (ulonglong2*)wm2;
        for (int i = t; i < 1536; i += 256) { sa[i] = a[i]; sb[i] = b[i]; }
        for (int i = t; i < 640;  i += 256) sc[i] = c[i];
        for (int i = t; i < 800;  i += 256) sd[i] = d[i];
    }
    __syncthreads();

    int lane = t & 31;
    int warp = t >> 5;
    int n0 = blockIdx.x * 32 + warp * 4;
    ull* my = &stg[warp * 128];      // a01[32] a23[32] h01[32] h23[32]
    float* myf = (float*)my;

#pragma unroll
    for (int i = 0; i < 4; i++) {
        int idx = (n0 + i) * 32 + lane;
        float av = g_agg1[idx];
        float hv = g_h1[idx];
        myf[(((i >> 1) * 32) + lane) * 2 + (i & 1)] = av;
        myf[((64 + (i >> 1) * 32) + lane) * 2 + (i & 1)] = hv;
    }
    __syncwarp();

    float b_ir = bih[lane], b_iz = bih[32 + lane], b_in = bih[64 + lane];
    float b_hr = bhh[lane], b_hz = bhh[32 + lane], b_hn = bhh[64 + lane];
    ull gir01 = pack2(b_ir, b_ir), gir23 = gir01;
    ull giz01 = pack2(b_iz, b_iz), giz23 = giz01;
    ull gin01 = pack2(b_in, b_in), gin23 = gin01;
    ull ghr01 = pack2(b_hr, b_hr), ghr23 = ghr01;
    ull ghz01 = pack2(b_hz, b_hz), ghz23 = ghz01;
    ull ghn01 = pack2(b_hn, b_hn), ghn23 = ghn01;

#pragma unroll 4
    for (int k = 0; k < 32; k++) {
        ull a01 = my[k], a23 = my[32 + k], h01 = my[64 + k], h23 = my[96 + k];
        const ull* wik = &wi2[k * 96];
        const ull* whk = &wh2[k * 96];
        ull wir = wik[lane], wiz = wik[32 + lane], win = wik[64 + lane];
        ull whr = whk[lane], whz = whk[32 + lane], whn = whk[64 + lane];
        fma2(gir01, a01, wir); fma2(gir23, a23, wir);
        fma2(giz01, a01, wiz); fma2(giz23, a23, wiz);
        fma2(gin01, a01, win); fma2(gin23, a23, win);
        fma2(ghr01, h01, whr); fma2(ghr23, h23, whr);
        fma2(ghz01, h01, whz); fma2(ghz23, h23, whz);
        fma2(ghn01, h01, whn); fma2(ghn23, h23, whn);
    }

    float gir[4], giz[4], gin[4], ghr[4], ghz[4], ghn[4], hvv[4], hr[4];
    unpack2(gir01, gir[0], gir[1]); unpack2(gir23, gir[2], gir[3]);
    unpack2(giz01, giz[0], giz[1]); unpack2(giz23, giz[2], giz[3]);
    unpack2(gin01, gin[0], gin[1]); unpack2(gin23, gin[2], gin[3]);
    unpack2(ghr01, ghr[0], ghr[1]); unpack2(ghr23, ghr[2], ghr[3]);
    unpack2(ghz01, ghz[0], ghz[1]); unpack2(ghz23, ghz[2], ghz[3]);
    unpack2(ghn01, ghn[0], ghn[1]); unpack2(ghn23, ghn[2], ghn[3]);
#pragma unroll
    for (int i = 0; i < 4; i++) {
        hvv[i] = myf[((64 + (i >> 1) * 32) + lane) * 2 + (i & 1)];
        float r = 1.f / (1.f + __expf(-(gir[i] + ghr[i])));
        float z = 1.f / (1.f + __expf(-(giz[i] + ghz[i])));
        float n = tanhf(gin[i] + r * ghn[i]);
        hr[i] = fmaxf((1.f - z) * n + z * hvv[i], 0.f);
    }

    // stage hr packed (reuse a regions)
    __syncwarp();
    my[lane] = pack2(hr[0], hr[1]);
    my[32 + lane] = pack2(hr[2], hr[3]);
    __syncwarp();

    int c2 = 32 + (lane & 7);
    ull hlo01 = 0, hlo23 = 0, hhi01 = 0, hhi23 = 0;
#pragma unroll 8
    for (int k = 0; k < 32; k++) {
        ull i01 = my[k], i23 = my[32 + k];
        ull wlo = wp2[k * 40 + lane];
        ull whi = wp2[k * 40 + c2];
        fma2(hlo01, i01, wlo); fma2(hlo23, i23, wlo);
        fma2(hhi01, i01, whi); fma2(hhi23, i23, whi);
    }
    // stage h2 packed: hlo into [64..127], hhi into [0..7]/[32..39]
    __syncwarp();
    my[64 + lane] = hlo01;
    my[96 + lane] = hlo23;
    if (lane < 8) { my[lane] = hhi01; my[32 + lane] = hhi23; }
    __syncwarp();

    ull mlo01 = 0, mlo23 = 0, mhi01 = 0, mhi23 = 0;
#pragma unroll 8
    for (int k = 0; k < 32; k++) {
        ull i01 = my[64 + k], i23 = my[96 + k];
        ull wlo = wm2[k * 40 + lane];
        ull whi = wm2[k * 40 + c2];
        fma2(mlo01, i01, wlo); fma2(mlo23, i23, wlo);
        fma2(mhi01, i01, whi); fma2(mhi23, i23, whi);
    }
#pragma unroll
    for (int k = 32; k < 40; k++) {
        ull i01 = my[k - 32], i23 = my[k];   // hhi staged at [0..7] and [32..39]
        ull wlo = wm2[k * 40 + lane];
        ull whi = wm2[k * 40 + c2];
        fma2(mlo01, i01, wlo); fma2(mlo23, i23, wlo);
        fma2(mhi01, i01, whi); fma2(mhi23, i23, whi);
    }

    float hlo[4], hhi[4], mlo[4], mhi[4];
    unpack2(hlo01, hlo[0], hlo[1]); unpack2(hlo23, hlo[2], hlo[3]);
    unpack2(hhi01, hhi[0], hhi[1]); unpack2(hhi23, hhi[2], hhi[3]);
    unpack2(mlo01, mlo[0], mlo[1]); unpack2(mlo23, mlo[2], mlo[3]);
    unpack2(mhi01, mhi[0], mhi[1]); unpack2(mhi23, mhi[2], mhi[3]);
#pragma unroll
    for (int i = 0; i < 4; i++) {
        int base = (n0 + i) * 40;
        g_h2[base + lane] = hlo[i];
        g_m2[base + lane] = mlo[i];
        g_agg2[base + lane] = 0.f;
        if (lane < 8) {
            g_h2[base + 32 + lane] = hhi[i];
            g_m2[base + 32 + lane] = mhi[i];
            g_agg2[base + 32 + lane] = 0.f;
        }
    }
}

// ---------------- K4: edge scatter layer 2 (2 edges/thread, red.v4) ----------------
__global__ void k_edge2(const int* __restrict__ ei,
                        const float* __restrict__ ew) {
    int tid = blockIdx.x * 256 + threadIdx.x;
    int e = tid / 10;
    if (e >= N_EDGES / 2) return;
    int q = tid - e * 10;
    int e2 = e + N_EDGES / 2;
    int s0 = ei[e],  d0 = ei[N_EDGES + e];  float w0 = ew[e];
    int s1 = ei[e2], d1 = ei[N_EDGES + e2]; float w1 = ew[e2];
    float4 a = *(const float4*)&g_m2[s0 * 40 + q * 4];
    float4 b = *(const float4*)&g_m2[s1 * 40 + q * 4];
    a.x *= w0; a.y *= w0; a.z *= w0; a.w *= w0;
    b.x *= w1; b.y *= w1; b.z *= w1; b.w *= w1;
    red_add_v4(&g_agg2[d0 * 40 + q * 4], a);
    red_add_v4(&g_agg2[d1 * 40 + q * 4], b);
}

// ---------------- K5: GRU2 + log_softmax (f32x2, 4 nodes/warp) ----------------
__global__ void __launch_bounds__(256) k_gru2(float* __restrict__ out,
                       const float* __restrict__ bih,
                       const float* __restrict__ bhh) {
    extern __shared__ ull dyn2[];
    ull* wi2 = dyn2;                 // 40*120
    ull* wh2 = wi2 + 40 * 120;       // 40*120
    ull* stg = wh2 + 40 * 120;       // 8*160

    int t = threadIdx.x;
    {   // copy 9600 ull = 4800 ull2
        const ulonglong2* a = (const ulonglong2*)g_wi2pk;
        const ulonglong2* b = (const ulonglong2*)g_wh2pk;
        ulonglong2* sa = (ulonglong2*)wi2;
        ulonglong2* sb = (ulonglong2*)wh2;
        for (int i = t; i < 2400; i += 256) { sa[i] = a[i]; sb[i] = b[i]; }
    }
    __syncthreads();

    int lane = t & 31;
    int warp = t >> 5;
    int c2 = 32 + (lane & 7);
    int n0 = blockIdx.x * 32 + warp * 4;
    ull* my = &stg[warp * 160];      // a01[40] a23[40] h01[40] h23[40]
    float* myf = (float*)my;

#pragma unroll
    for (int i = 0; i < 4; i++) {
        int b = (n0 + i) * 40;
        float av = g_agg2[b + lane];
        float hv = g_h2[b + lane];
        myf[(((i >> 1) * 40) + lane) * 2 + (i & 1)] = av;
        myf[((80 + (i >> 1) * 40) + lane) * 2 + (i & 1)] = hv;
        if (lane < 8) {
            float avh = g_agg2[b + 32 + lane];
            float hvh = g_h2[b + 32 + lane];
            myf[(((i >> 1) * 40) + 32 + lane) * 2 + (i & 1)] = avh;
            myf[((80 + (i >> 1) * 40) + 32 + lane) * 2 + (i & 1)] = hvh;
        }
    }
    __syncwarp();

    float b0 = bih[lane], b1 = bih[40 + lane], b2 = bih[80 + lane];
    float b3 = bhh[lane], b4 = bhh[40 + lane], b5 = bhh[80 + lane];
    float c0 = bih[c2], c1 = bih[40 + c2], c3 = bih[80 + c2];
    float c4 = bhh[c2], c5 = bhh[40 + c2], c6 = bhh[80 + c2];

    ull gir01 = pack2(b0, b0), gir23 = gir01;
    ull giz01 = pack2(b1, b1), giz23 = giz01;
    ull gin01 = pack2(b2, b2), gin23 = gin01;
    ull ghr01 = pack2(b3, b3), ghr23 = ghr01;
    ull ghz01 = pack2(b4, b4), ghz23 = ghz01;
    ull ghn01 = pack2(b5, b5), ghn23 = ghn01;
    ull Gir01 = pack2(c0, c0), Gir23 = Gir01;
    ull Giz01 = pack2(c1, c1), Giz23 = Giz01;
    ull Gin01 = pack2(c3, c3), Gin23 = Gin01;
    ull Ghr01 = pack2(c4, c4), Ghr23 = Ghr01;
    ull Ghz01 = pack2(c5, c5), Ghz23 = Ghz01;
    ull Ghn01 = pack2(c6, c6), Ghn23 = Ghn01;

#pragma unroll 4
    for (int k = 0; k < 40; k++) {
        ull a01 = my[k], a23 = my[40 + k], h01 = my[80 + k], h23 = my[120 + k];
        const ull* wik = &wi2[k * 120];
        const ull* whk = &wh2[k * 120];
        ull wi0 = wik[lane], wi1 = wik[40 + lane], wi2v = wik[80 + lane];
        ull wj0 = wik[c2],   wj1 = wik[40 + c2],   wj2 = wik[80 + c2];
        ull wh0 = whk[lane], wh1 = whk[40 + lane], wh2v = whk[80 + lane];
        ull wg0 = whk[c2],   wg1 = whk[40 + c2],   wg2 = whk[80 + c2];
        fma2(gir01, a01, wi0); fma2(gir23, a23, wi0);
        fma2(giz01, a01, wi1); fma2(giz23, a23, wi1);
        fma2(gin01, a01, wi2v); fma2(gin23, a23, wi2v);
        fma2(Gir01, a01, wj0); fma2(Gir23, a23, wj0);
        fma2(Giz01, a01, wj1); fma2(Giz23, a23, wj1);
        fma2(Gin01, a01, wj2); fma2(Gin23, a23, wj2);
        fma2(ghr01, h01, wh0); fma2(ghr23, h23, wh0);
        fma2(ghz01, h01, wh1); fma2(ghz23, h23, wh1);
        fma2(ghn01, h01, wh2v); fma2(ghn23, h23, wh2v);
        fma2(Ghr01, h01, wg0); fma2(Ghr23, h23, wg0);
        fma2(Ghz01, h01, wg1); fma2(Ghz23, h23, wg1);
        fma2(Ghn01, h01, wg2); fma2(Ghn23, h23, wg2);
    }

    float gir[4], giz[4], gin[4], ghr[4], ghz[4], ghn[4];
    float Gir[4], Giz[4], Gin[4], Ghr[4], Ghz[4], Ghn[4];
    unpack2(gir01, gir[0], gir[1]); unpack2(gir23, gir[2], gir[3]);
    unpack2(giz01, giz[0], giz[1]); unpack2(giz23, giz[2], giz[3]);
    unpack2(gin01, gin[0], gin[1]); unpack2(gin23, gin[2], gin[3]);
    unpack2(ghr01, ghr[0], ghr[1]); unpack2(ghr23, ghr[2], ghr[3]);
    unpack2(ghz01, ghz[0], ghz[1]); unpack2(ghz23, ghz[2], ghz[3]);
    unpack2(ghn01, ghn[0], ghn[1]); unpack2(ghn23, ghn[2], ghn[3]);
    unpack2(Gir01, Gir[0], Gir[1]); unpack2(Gir23, Gir[2], Gir[3]);
    unpack2(Giz01, Giz[0], Giz[1]); unpack2(Giz23, Giz[2], Giz[3]);
    unpack2(Gin01, Gin[0], Gin[1]); unpack2(Gin23, Gin[2], Gin[3]);
    unpack2(Ghr01, Ghr[0], Ghr[1]); unpack2(Ghr23, Ghr[2], Ghr[3]);
    unpack2(Ghz01, Ghz[0], Ghz[1]); unpack2(Ghz23, Ghz[2], Ghz[3]);
    unpack2(Ghn01, Ghn[0], Ghn[1]); unpack2(Ghn23, Ghn[2], Ghn[3]);

#pragma unroll
    for (int i = 0; i < 4; i++) {
        float h_lo = myf[((80 + (i >> 1) * 40) + lane) * 2 + (i & 1)];
        float h_hi = (lane < 8) ? myf[((80 + (i >> 1) * 40) + 32 + lane) * 2 + (i & 1)] : 0.f;

        float r1 = 1.f / (1.f + __expf(-(gir[i] + ghr[i])));
        float z1 = 1.f / (1.f + __expf(-(giz[i] + ghz[i])));
        float n1 = tanhf(gin[i] + r1 * ghn[i]);
        float v1 = (1.f - z1) * n1 + z1 * h_lo;

        float r2 = 1.f / (1.f + __expf(-(Gir[i] + Ghr[i])));
        float z2 = 1.f / (1.f + __expf(-(Giz[i] + Ghz[i])));
        float n2 = tanhf(Gin[i] + r2 * Ghn[i]);
        float v2 = (1.f - z2) * n2 + z2 * h_hi;

        float vmax = fmaxf(v1, (lane < 8) ? v2 : -FLT_MAX);
#pragma unroll
        for (int o = 16; o > 0; o >>= 1)
            vmax = fmaxf(vmax, __shfl_xor_sync(0xffffffffu, vmax, o));
        float se = __expf(v1 - vmax) + ((lane < 8) ? __expf(v2 - vmax) : 0.f);
#pragma unroll
        for (int o = 16; o > 0; o >>= 1)
            se += __shfl_xor_sync(0xffffffffu, se, o);
        float ls = vmax + logf(se);

        int b = (n0 + i) * 40;
        out[b + lane] = v1 - ls;
        if (lane < 8) out[b + 32 + lane] = v2 - ls;
    }
}

// ---------------- launch ----------------
extern "C" void kernel_launch(void* const* d_in, const int* in_sizes, int n_in,
                              void* d_out, int out_size) {
    const float* x   = (const float*)d_in[0];
    const int*   ei  = (const int*)d_in[1];     // int32 (JAX x64 disabled)
    const float* ew  = (const float*)d_in[2];
    const float* W1p = (const float*)d_in[3];
    const float* W1m = (const float*)d_in[4];
    const float* g1wih = (const float*)d_in[5];
    const float* g1whh = (const float*)d_in[6];
    const float* g1bih = (const float*)d_in[7];
    const float* g1bhh = (const float*)d_in[8];
    const float* W2p = (const float*)d_in[9];
    const float* W2m = (const float*)d_in[10];
    const float* g2wih = (const float*)d_in[11];
    const float* g2whh = (const float*)d_in[12];
    const float* g2bih = (const float*)d_in[13];
    const float* g2bhh = (const float*)d_in[14];
    float* out = (float*)d_out;

    const int smem1 = (32*96*2 + 32*40 + 40*40 + 8*128) * 8;   // 80384 B
    const int smem2 = (40*120*2 + 8*160) * 8;                  // 87040 B
    cudaFuncSetAttribute(k_gru1_proj2, cudaFuncAttributeMaxDynamicSharedMemorySize, smem1);
    cudaFuncSetAttribute(k_gru2,       cudaFuncAttributeMaxDynamicSharedMemorySize, smem2);

    k_prepack<<<64, 256>>>(W1p, W1m, g1wih, g1whh, W2p, W2m, g2wih, g2whh);

    k_proj1<<<NODE_BLOCKS, 256>>>(x);

    k_edge1<<<(N_EDGES / 2) * 8 / 256, 256>>>(ei, ew);          // 31250 blocks

    k_gru1_proj2<<<NODE_BLOCKS, 256, smem1>>>(g1bih, g1bhh);

    k_edge2<<<((N_EDGES / 2) * 10 + 255) / 256, 256>>>(ei, ew); // 39063 blocks

    k_gru2<<<NODE_BLOCKS, 256, smem2>>>(out, g2bih, g2bhh);
}

// round 9
// speedup vs baseline: 1.1344x; 1.1344x over previous
#include <cuda_runtime.h>
#include <cstdint>
#include <float.h>

#define N_NODES 100000
#define N_EDGES 2000000
#define HID 32
#define NCLS 40
#define NODE_BLOCKS 3125   // 100000 / 32 nodes per block (8 warps x 4 nodes)

// ---------------- scratch (static device memory; no allocation) ----------------
__device__ float g_h1 [N_NODES * HID];
__device__ float g_m1 [N_NODES * HID];
__device__ float g_agg1[N_NODES * HID];
__device__ float g_h2 [N_NODES * NCLS];
__device__ float g_m2 [N_NODES * NCLS];
__device__ float g_agg2[N_NODES * NCLS];

__device__ __forceinline__ void red_add_v4(float* addr, float4 v) {
    asm volatile("red.global.add.v4.f32 [%0], {%1,%2,%3,%4};"
                 :: "l"(addr), "f"(v.x), "f"(v.y), "f"(v.z), "f"(v.w)
                 : "memory");
}

// ---------------- K1: h1 = x@W1p, m1 = h1@W1m, zero agg1 (4 nodes/warp) --------
__global__ void __launch_bounds__(256) k_proj1(const float* __restrict__ x,
                        const float* __restrict__ Wp,
                        const float* __restrict__ Wm) {
    __shared__ float sWp[1024];
    __shared__ float sWm[1024];
    int t = threadIdx.x;
    for (int i = t; i < 1024; i += 256) { sWp[i] = Wp[i]; sWm[i] = Wm[i]; }
    __syncthreads();

    int lane = t & 31;
    int n0 = blockIdx.x * 32 + (t >> 5) * 4;

    float xv[4], h[4], m[4];
#pragma unroll
    for (int i = 0; i < 4; i++) { xv[i] = x[(n0 + i) * 32 + lane]; h[i] = 0.f; m[i] = 0.f; }

#pragma unroll
    for (int k = 0; k < 32; k++) {
        float w = sWp[k * 32 + lane];
#pragma unroll
        for (int i = 0; i < 4; i++)
            h[i] = fmaf(__shfl_sync(0xffffffffu, xv[i], k), w, h[i]);
    }
#pragma unroll
    for (int k = 0; k < 32; k++) {
        float w = sWm[k * 32 + lane];
#pragma unroll
        for (int i = 0; i < 4; i++)
            m[i] = fmaf(__shfl_sync(0xffffffffu, h[i], k), w, m[i]);
    }
#pragma unroll
    for (int i = 0; i < 4; i++) {
        int idx = (n0 + i) * 32 + lane;
        g_h1[idx] = h[i];
        g_m1[idx] = m[i];
        g_agg1[idx] = 0.f;
    }
}

// ---------------- K2: edge scatter layer 1 — 8 threads/edge, float4 + red.v4 ----
__global__ void k_edge1(const int* __restrict__ ei,
                        const float* __restrict__ ew) {
    long long tid = (long long)blockIdx.x * blockDim.x + threadIdx.x;
    int e = (int)(tid >> 3);
    if (e >= N_EDGES) return;
    int q = (int)(tid & 7);
    int src = ei[e];
    int dst = ei[N_EDGES + e];
    float w = ew[e];
    const float4* mrow = (const float4*)&g_m1[src * 32];
    float4 m = mrow[q];
    m.x *= w; m.y *= w; m.z *= w; m.w *= w;
    red_add_v4(&g_agg1[dst * 32 + q * 4], m);
}

// ------- K3: GRU1 + ReLU + proj2 + msg2 fused, zero agg2 (4 nodes/warp) --------
__global__ void __launch_bounds__(256) k_gru1_proj2(
                             const float* __restrict__ wih,
                             const float* __restrict__ whh,
                             const float* __restrict__ bih,
                             const float* __restrict__ bhh,
                             const float* __restrict__ Wp,
                             const float* __restrict__ Wm) {
    __shared__ float sWi[32 * 97]; // transposed [k][r], padded
    __shared__ float sWh[32 * 97];
    __shared__ float sWp[32 * 40];
    __shared__ float sWm[40 * 40];
    int t = threadIdx.x;
    for (int i = t; i < 96 * 32; i += 256) {
        int r = i >> 5, k = i & 31;
        sWi[k * 97 + r] = wih[i];
        sWh[k * 97 + r] = whh[i];
    }
    for (int i = t; i < 32 * 40; i += 256) sWp[i] = Wp[i];
    for (int i = t; i < 40 * 40; i += 256) sWm[i] = Wm[i];
    __syncthreads();

    int lane = t & 31;
    int n0 = blockIdx.x * 32 + (t >> 5) * 4;

    float a[4], hv[4];
    float gir[4], giz[4], gin[4], ghr[4], ghz[4], ghn[4];
    float b_ir = bih[lane], b_iz = bih[32 + lane], b_in = bih[64 + lane];
    float b_hr = bhh[lane], b_hz = bhh[32 + lane], b_hn = bhh[64 + lane];
#pragma unroll
    for (int i = 0; i < 4; i++) {
        int idx = (n0 + i) * 32 + lane;
        a[i] = g_agg1[idx];
        hv[i] = g_h1[idx];
        gir[i] = b_ir; giz[i] = b_iz; gin[i] = b_in;
        ghr[i] = b_hr; ghz[i] = b_hz; ghn[i] = b_hn;
    }

#pragma unroll 8
    for (int k = 0; k < 32; k++) {
        const float* wi = &sWi[k * 97];
        const float* wh = &sWh[k * 97];
        float wir = wi[lane], wiz = wi[32 + lane], win = wi[64 + lane];
        float whr = wh[lane], whz = wh[32 + lane], whn = wh[64 + lane];
#pragma unroll
        for (int i = 0; i < 4; i++) {
            float ak = __shfl_sync(0xffffffffu, a[i],  k);
            float hk = __shfl_sync(0xffffffffu, hv[i], k);
            gir[i] = fmaf(ak, wir, gir[i]);
            giz[i] = fmaf(ak, wiz, giz[i]);
            gin[i] = fmaf(ak, win, gin[i]);
            ghr[i] = fmaf(hk, whr, ghr[i]);
            ghz[i] = fmaf(hk, whz, ghz[i]);
            ghn[i] = fmaf(hk, whn, ghn[i]);
        }
    }

    float hr[4];
#pragma unroll
    for (int i = 0; i < 4; i++) {
        float r = 1.f / (1.f + __expf(-(gir[i] + ghr[i])));
        float z = 1.f / (1.f + __expf(-(giz[i] + ghz[i])));
        float n = tanhf(gin[i] + r * ghn[i]);
        hr[i] = fmaxf((1.f - z) * n + z * hv[i], 0.f);
    }

    // ---- proj2: h2 = hr@Wp (32->40), m2 = h2@Wm (40->40) ----
    int c2 = 32 + (lane & 7);
    float h_lo[4] = {0,0,0,0}, h_hi[4] = {0,0,0,0};
#pragma unroll 8
    for (int k = 0; k < 32; k++) {
        float wlo = sWp[k * 40 + lane];
        float whi = sWp[k * 40 + c2];
#pragma unroll
        for (int i = 0; i < 4; i++) {
            float ak = __shfl_sync(0xffffffffu, hr[i], k);
            h_lo[i] = fmaf(ak, wlo, h_lo[i]);
            h_hi[i] = fmaf(ak, whi, h_hi[i]);
        }
    }
    float m_lo[4] = {0,0,0,0}, m_hi[4] = {0,0,0,0};
#pragma unroll 8
    for (int k = 0; k < 32; k++) {
        float wlo = sWm[k * 40 + lane];
        float whi = sWm[k * 40 + c2];
#pragma unroll
        for (int i = 0; i < 4; i++) {
            float hk = __shfl_sync(0xffffffffu, h_lo[i], k);
            m_lo[i] = fmaf(hk, wlo, m_lo[i]);
            m_hi[i] = fmaf(hk, whi, m_hi[i]);
        }
    }
#pragma unroll
    for (int k = 0; k < 8; k++) {
        float wlo = sWm[(32 + k) * 40 + lane];
        float whi = sWm[(32 + k) * 40 + c2];
#pragma unroll
        for (int i = 0; i < 4; i++) {
            float hk = __shfl_sync(0xffffffffu, h_hi[i], k);
            m_lo[i] = fmaf(hk, wlo, m_lo[i]);
            m_hi[i] = fmaf(hk, whi, m_hi[i]);
        }
    }
#pragma unroll
    for (int i = 0; i < 4; i++) {
        int base = (n0 + i) * 40;
        g_h2[base + lane] = h_lo[i];
        g_m2[base + lane] = m_lo[i];
        g_agg2[base + lane] = 0.f;
        if (lane < 8) {
            g_h2[base + 32 + lane] = h_hi[i];
            g_m2[base + 32 + lane] = m_hi[i];
            g_agg2[base + 32 + lane] = 0.f;
        }
    }
}

// ---------------- K4: edge scatter layer 2 — 10 threads/edge, float4 + red.v4 ----
__global__ void k_edge2(const int* __restrict__ ei,
                        const float* __restrict__ ew) {
    long long tid = (long long)blockIdx.x * blockDim.x + threadIdx.x;
    int e = (int)(tid / 10);
    if (e >= N_EDGES) return;
    int q = (int)(tid - (long long)e * 10);
    int src = ei[e];
    int dst = ei[N_EDGES + e];
    float w = ew[e];
    const float4* mrow = (const float4*)&g_m2[src * 40];
    float4 m = mrow[q];
    m.x *= w; m.y *= w; m.z *= w; m.w *= w;
    red_add_v4(&g_agg2[dst * 40 + q * 4], m);
}

// -------- K5: GRU2 + log_softmax (4 nodes/warp, exact-fit hi pass) ----------
// lo pass: lanes = cols 0..31, 4 nodes (full fill, shfl inputs).
// hi pass: lane -> (node = lane>>3, col = 32+(lane&7)), inputs via smem staging.
__global__ void __launch_bounds__(256) k_gru2(float* __restrict__ out,
                       const float* __restrict__ wih,
                       const float* __restrict__ whh,
                       const float* __restrict__ bih,
                       const float* __restrict__ bhh) {
    extern __shared__ float dyn[];
    float* sWi = dyn;                  // 40*121  [k][row], padded
    float* sWh = sWi + 40 * 121;       // 40*121
    float* sStage = sWh + 40 * 121;    // 8 warps * 2 * 164 (sA[4*41], sH[4*41])

    int t = threadIdx.x;
    for (int i = t; i < 120 * 40; i += 256) {
        int r = i / 40, k = i % 40;
        sWi[k * 121 + r] = wih[i];
        sWh[k * 121 + r] = whh[i];
    }
    __syncthreads();

    int lane = t & 31;
    int warp = t >> 5;
    int n0 = blockIdx.x * 32 + warp * 4;
    float* sA = sStage + warp * 328;
    float* sH = sA + 164;

    // stage inputs + keep lo/hi shfl-source registers
    float a_lo[4], h_lo[4], a_hi[4], h_hi[4];
#pragma unroll
    for (int i = 0; i < 4; i++) {
        int b = (n0 + i) * 40;
        float av = g_agg2[b + lane];
        float hvv = g_h2[b + lane];
        a_lo[i] = av; h_lo[i] = hvv;
        sA[i * 41 + lane] = av;
        sH[i * 41 + lane] = hvv;
        if (lane < 8) {
            float avh = g_agg2[b + 32 + lane];
            float hvh = g_h2[b + 32 + lane];
            a_hi[i] = avh; h_hi[i] = hvh;
            sA[i * 41 + 32 + lane] = avh;
            sH[i * 41 + 32 + lane] = hvh;
        } else { a_hi[i] = 0.f; h_hi[i] = 0.f; }
    }
    __syncwarp();

    // lo accumulators (col = lane, 4 nodes)
    float gir[4], giz[4], gin[4], ghr[4], ghz[4], ghn[4];
    {
        float b0 = bih[lane], b1 = bih[40 + lane], b2 = bih[80 + lane];
        float b3 = bhh[lane], b4 = bhh[40 + lane], b5 = bhh[80 + lane];
#pragma unroll
        for (int i = 0; i < 4; i++) {
            gir[i] = b0; giz[i] = b1; gin[i] = b2;
            ghr[i] = b3; ghz[i] = b4; ghn[i] = b5;
        }
    }
    // hi accumulators (1 slot/lane: node=lane>>3, col=32+(lane&7))
    int hi_node = lane >> 3;
    int hi_col  = 32 + (lane & 7);
    float Gir = bih[hi_col], Giz = bih[40 + hi_col], Gin = bih[80 + hi_col];
    float Ghr = bhh[hi_col], Ghz = bhh[40 + hi_col], Ghn = bhh[80 + hi_col];
    const float* aN = sA + hi_node * 41;
    const float* hN = sH + hi_node * 41;

#pragma unroll 4
    for (int k = 0; k < 32; k++) {
        const float* wi = &sWi[k * 121];
        const float* wh = &sWh[k * 121];
        float wi0 = wi[lane], wi1 = wi[40 + lane], wi2 = wi[80 + lane];
        float wh0 = wh[lane], wh1 = wh[40 + lane], wh2 = wh[80 + lane];
        // hi slot
        {
            float ak = aN[k], hk = hN[k];
            Gir = fmaf(ak, wi[hi_col],      Gir);
            Giz = fmaf(ak, wi[40 + hi_col], Giz);
            Gin = fmaf(ak, wi[80 + hi_col], Gin);
            Ghr = fmaf(hk, wh[hi_col],      Ghr);
            Ghz = fmaf(hk, wh[40 + hi_col], Ghz);
            Ghn = fmaf(hk, wh[80 + hi_col], Ghn);
        }
#pragma unroll
        for (int i = 0; i < 4; i++) {
            float ak = __shfl_sync(0xffffffffu, a_lo[i], k);
            float hk = __shfl_sync(0xffffffffu, h_lo[i], k);
            gir[i] = fmaf(ak, wi0, gir[i]);
            giz[i] = fmaf(ak, wi1, giz[i]);
            gin[i] = fmaf(ak, wi2, gin[i]);
            ghr[i] = fmaf(hk, wh0, ghr[i]);
            ghz[i] = fmaf(hk, wh1, ghz[i]);
            ghn[i] = fmaf(hk, wh2, ghn[i]);
        }
    }
#pragma unroll
    for (int k = 32; k < 40; k++) {
        const float* wi = &sWi[k * 121];
        const float* wh = &sWh[k * 121];
        float wi0 = wi[lane], wi1 = wi[40 + lane], wi2 = wi[80 + lane];
        float wh0 = wh[lane], wh1 = wh[40 + lane], wh2 = wh[80 + lane];
        {
            float ak = aN[k], hk = hN[k];
            Gir = fmaf(ak, wi[hi_col],      Gir);
            Giz = fmaf(ak, wi[40 + hi_col], Giz);
            Gin = fmaf(ak, wi[80 + hi_col], Gin);
            Ghr = fmaf(hk, wh[hi_col],      Ghr);
            Ghz = fmaf(hk, wh[40 + hi_col], Ghz);
            Ghn = fmaf(hk, wh[80 + hi_col], Ghn);
        }
#pragma unroll
        for (int i = 0; i < 4; i++) {
            float ak = __shfl_sync(0xffffffffu, a_hi[i], k - 32);
            float hk = __shfl_sync(0xffffffffu, h_hi[i], k - 32);
            gir[i] = fmaf(ak, wi0, gir[i]);
            giz[i] = fmaf(ak, wi1, giz[i]);
            gin[i] = fmaf(ak, wi2, gin[i]);
            ghr[i] = fmaf(hk, wh0, ghr[i]);
            ghz[i] = fmaf(hk, wh1, ghz[i]);
            ghn[i] = fmaf(hk, wh2, ghn[i]);
        }
    }

    // lo outputs
    float v1[4];
#pragma unroll
    for (int i = 0; i < 4; i++) {
        float r1 = 1.f / (1.f + __expf(-(gir[i] + ghr[i])));
        float z1 = 1.f / (1.f + __expf(-(giz[i] + ghz[i])));
        float n1 = tanhf(gin[i] + r1 * ghn[i]);
        v1[i] = (1.f - z1) * n1 + z1 * h_lo[i];
    }
    // hi output (one per lane)
    float v2;
    {
        float hvh = sH[hi_node * 41 + hi_col];
        float r2 = 1.f / (1.f + __expf(-(Gir + Ghr)));
        float z2 = 1.f / (1.f + __expf(-(Giz + Ghz)));
        float n2 = tanhf(Gin + r2 * Ghn);
        v2 = (1.f - z2) * n2 + z2 * hvh;
    }

    // stage v into sA (reuse) and do per-node log_softmax
    __syncwarp();
#pragma unroll
    for (int i = 0; i < 4; i++) sA[i * 41 + lane] = v1[i];
    sA[hi_node * 41 + hi_col] = v2;
    __syncwarp();

#pragma unroll
    for (int i = 0; i < 4; i++) {
        float x1 = sA[i * 41 + lane];
        float x2 = (lane < 8) ? sA[i * 41 + 32 + lane] : -FLT_MAX;
        float vmax = fmaxf(x1, x2);
#pragma unroll
        for (int o = 16; o > 0; o >>= 1)
            vmax = fmaxf(vmax, __shfl_xor_sync(0xffffffffu, vmax, o));
        float se = __expf(x1 - vmax) + ((lane < 8) ? __expf(x2 - vmax) : 0.f);
#pragma unroll
        for (int o = 16; o > 0; o >>= 1)
            se += __shfl_xor_sync(0xffffffffu, se, o);
        float ls = vmax + logf(se);

        int b = (n0 + i) * 40;
        out[b + lane] = x1 - ls;
        if (lane < 8) out[b + 32 + lane] = x2 - ls;
    }
}

// ---------------- launch ----------------
extern "C" void kernel_launch(void* const* d_in, const int* in_sizes, int n_in,
                              void* d_out, int out_size) {
    const float* x   = (const float*)d_in[0];
    const int*   ei  = (const int*)d_in[1];     // int32 (JAX x64 disabled)
    const float* ew  = (const float*)d_in[2];
    const float* W1p = (const float*)d_in[3];
    const float* W1m = (const float*)d_in[4];
    const float* g1wih = (const float*)d_in[5];
    const float* g1whh = (const float*)d_in[6];
    const float* g1bih = (const float*)d_in[7];
    const float* g1bhh = (const float*)d_in[8];
    const float* W2p = (const float*)d_in[9];
    const float* W2m = (const float*)d_in[10];
    const float* g2wih = (const float*)d_in[11];
    const float* g2whh = (const float*)d_in[12];
    const float* g2bih = (const float*)d_in[13];
    const float* g2bhh = (const float*)d_in[14];
    float* out = (float*)d_out;

    const int smem2 = (40 * 121 * 2 + 8 * 328) * 4;   // 49216 B
    cudaFuncSetAttribute(k_gru2, cudaFuncAttributeMaxDynamicSharedMemorySize, smem2);

    k_proj1<<<NODE_BLOCKS, 256>>>(x, W1p, W1m);

    long long th1 = (long long)N_EDGES * 8;
    k_edge1<<<(int)((th1 + 255) / 256), 256>>>(ei, ew);

    k_gru1_proj2<<<NODE_BLOCKS, 256>>>(g1wih, g1whh, g1bih, g1bhh, W2p, W2m);

    long long th2 = (long long)N_EDGES * 10;
    k_edge2<<<(int)((th2 + 255) / 256), 256>>>(ei, ew);

    k_gru2<<<NODE_BLOCKS, 256, smem2>>>(out, g2bih ? g2wih : g2wih, g2whh, g2bih, g2bhh);
}